// round 15
// baseline (speedup 1.0000x reference)
#include <cuda_runtime.h>
#include <math.h>
#include <stdint.h>

constexpr int cB=64, cS=196, cH=1024, cK=2048, cV=10000, cE=512, cT=16, cTS=15;
constexpr int BSR = cB*cS;            // 12544
constexpr int MT  = cTS*cB;           // 960
constexpr int L0SZ = 128*3072*32;
constexpr int LSZ  = 128*2048*32;
constexpr int QSZ  = 32*1024*32;
constexpr int NB   = 148;

__device__ unsigned g_cnt, g_gen;

__device__ float g_Bp0[L0SZ];
__device__ float g_Bp123[3*LSZ];
__device__ float g_Wqp[QSZ];
__device__ float g_biasp[4*4096];
__device__ float g_Bcat[2048*2048];   // rounded
__device__ float g_bcat[2048];
__device__ float g_featR[BSR*2048];   // rounded features
__device__ float g_fc1R[512*1024];
__device__ float g_fc2R[1024*10000];
__device__ float g_kf[BSR*2048];      // [keys | feat0]
__device__ float g_xemb[MT*cE];       // rounded
__device__ float g_xseq[MT*cH];
__device__ float g_cat0[2*64*3072];
__device__ float g_cat1[2*64*2048];
__device__ float g_cat2[2*64*2048];
__device__ float g_cat3[2*64*2048];
__device__ float g_q[64*1024];
__device__ float g_hall[MT*cH];       // rounded (epilogue)

__device__ __forceinline__ uint32_t f2tf(float f){
    uint32_t u; asm("cvt.rna.tf32.f32 %0,%1;":"=r"(u):"f"(f)); return u;
}
__device__ __forceinline__ float rnd(float f){ return __uint_as_float(f2tf(f)); }
__device__ __forceinline__ void mma8(float* d, const uint32_t* a, const uint32_t* b){
    asm volatile("mma.sync.aligned.m16n8k8.row.col.f32.tf32.tf32.f32 "
        "{%0,%1,%2,%3},{%4,%5,%6,%7},{%8,%9},{%0,%1,%2,%3};"
        : "+f"(d[0]),"+f"(d[1]),"+f"(d[2]),"+f"(d[3])
        : "r"(a[0]),"r"(a[1]),"r"(a[2]),"r"(a[3]),"r"(b[0]),"r"(b[1]));
}
__device__ __forceinline__ void cpa(void* s, const void* g){
    unsigned sa=(unsigned)__cvta_generic_to_shared(s);
    asm volatile("cp.async.ca.shared.global [%0],[%1],16;"::"r"(sa),"l"(g));
}
__device__ __forceinline__ void cpaz(void* s, const void* g, bool p){
    unsigned sa=(unsigned)__cvta_generic_to_shared(s);
    int sz=p?16:0;
    asm volatile("cp.async.ca.shared.global [%0],[%1],16,%2;"::"r"(sa),"l"(g),"r"(sz));
}
__device__ __forceinline__ float sigm(float x){ return 1.f/(1.f+expf(-x)); }
__device__ __forceinline__ float tanha(float x){
    float y; asm("tanh.approx.f32 %0,%1;":"=f"(y):"f"(x)); return y;
}

// ---------- replay-safe grid barrier ----------
__device__ __forceinline__ void gbar(){
    __syncthreads();
    if(threadIdx.x==0){
        __threadfence();
        unsigned g=*((volatile unsigned*)&g_gen);
        if(atomicAdd(&g_cnt,1)==gridDim.x-1){
            g_cnt=0;
            __threadfence();
            atomicAdd(&g_gen,1);
        } else {
            while(*((volatile unsigned*)&g_gen)==g){}
            __threadfence();
        }
    }
    __syncthreads();
}

// ---------- big tf32 GEMM (pre-rounded inputs; Bs padded conflict-free) ----------
template<int MODE>
__global__ __launch_bounds__(256) void k_mm(
    const float* __restrict__ A, const float* __restrict__ B,
    float* __restrict__ C, int M, int N, int K, const float* __restrict__ bias)
{
    __shared__ __align__(16) float As[4][128][20];
    __shared__ __align__(16) float Bs[4][16][136];
    const int tid=threadIdx.x, w=tid>>5, lane=tid&31, g=lane>>2, cl=lane&3;
    const int m0=blockIdx.y*128, n0=blockIdx.x*128;
    const int wm=(w>>2)*64, wn=(w&3)*32;
    float d[4][4][4];
#pragma unroll
    for(int mi=0;mi<4;mi++)
#pragma unroll
        for(int ni=0;ni<4;ni++)
#pragma unroll
            for(int k=0;k<4;k++) d[mi][ni][k]=0.f;

    const int nk=K>>4;
    auto LD=[&](int s,int kb){
#pragma unroll
        for(int i=0;i<2;i++){
            int r=i*64+(tid>>2), ch=(tid&3)*4;
            bool p=(m0+r)<M;
            int row=p?(m0+r):0;
            cpaz(&As[s][r][ch], A+(size_t)row*K+kb+ch, p);
        }
#pragma unroll
        for(int i=0;i<2;i++){
            int id=i*256+tid, r=id>>5, ch=(id&31)*4;
            bool p=(n0+ch)<N;
            int col=p?(n0+ch):0;
            cpaz(&Bs[s][r][ch], B+(size_t)(kb+r)*N+col, p);
        }
    };
#pragma unroll
    for(int s=0;s<3;s++){
        if(s<nk) LD(s,s*16);
        asm volatile("cp.async.commit_group;");
    }
    for(int i=0;i<nk;i++){
        asm volatile("cp.async.wait_group 2;");
        __syncthreads();
        const int st=i&3;
#pragma unroll
        for(int kc=0;kc<16;kc+=8){
            uint32_t a[4][4], b[4][2];
#pragma unroll
            for(int mi=0;mi<4;mi++){
                a[mi][0]=__float_as_uint(As[st][wm+16*mi+g][kc+cl]);
                a[mi][1]=__float_as_uint(As[st][wm+16*mi+8+g][kc+cl]);
                a[mi][2]=__float_as_uint(As[st][wm+16*mi+g][kc+cl+4]);
                a[mi][3]=__float_as_uint(As[st][wm+16*mi+8+g][kc+cl+4]);
            }
#pragma unroll
            for(int ni=0;ni<4;ni++){
                b[ni][0]=__float_as_uint(Bs[st][kc+cl][wn+8*ni+g]);
                b[ni][1]=__float_as_uint(Bs[st][kc+cl+4][wn+8*ni+g]);
            }
#pragma unroll
            for(int mi=0;mi<4;mi++)
#pragma unroll
                for(int ni=0;ni<4;ni++) mma8(d[mi][ni],a[mi],b[ni]);
        }
        int nx=i+3;
        if(nx<nk) LD(nx&3,nx*16);
        asm volatile("cp.async.commit_group;");
    }
#pragma unroll
    for(int mi=0;mi<4;mi++)
#pragma unroll
        for(int ni=0;ni<4;ni++)
#pragma unroll
            for(int k=0;k<4;k++){
                int row=m0+wm+16*mi+g+((k>=2)?8:0);
                int col=n0+wn+8*ni+2*cl+(k&1);
                if(row<M && col<N){
                    float v=d[mi][ni][k]+bias[col];
                    if(MODE==0) C[(size_t)row*N+col]=v;
                    else        C[(size_t)((row&63)*cTS+(row>>6))*N+col]=v;
                }
            }
}

// ---------- strip GEMM: R11 version (256 thr, 4-stage ring, inline 3xtf32) ----------
__device__ void strip_gemm(int epi, int n,
    const float* __restrict__ A, int lda, int KA,
    const float* __restrict__ Bg, int ldb, int boff,
    const float* __restrict__ bias,
    const float* __restrict__ hold, int ldh,
    float* __restrict__ o1, int ldo1,
    float* __restrict__ o2, int ldo2, int rnd2,
    float* As, float* Bs, float* Cs)
{
    const int tid=threadIdx.x;
    const float* Bblk=Bg+(size_t)n*boff;
    const int w=tid>>5, lane=tid&31, g=lane>>2, cl=lane&3;
    const int mt=w&3, nh=w>>2;
    float d[2][4]={{0.f,0.f,0.f,0.f},{0.f,0.f,0.f,0.f}};
    const int nkb=KA>>5;                 // BK=32
    auto LD=[&](int s,int kb){
#pragma unroll
        for(int i=0;i<2;i++){
            int q=i*256+tid, r=q>>3, ch=(q&7)*4;
            cpa(As+s*2304+r*36+ch, A+(size_t)r*lda+kb+ch);
        }
        { int r=tid>>3, ch=(tid&7)*4;
          cpa(Bs+s*1280+r*40+ch, Bblk+(size_t)(kb+r)*ldb+ch); }
    };
#pragma unroll
    for(int s=0;s<3;s++){
        if(s<nkb) LD(s,s*32);
        asm volatile("cp.async.commit_group;");
    }
    for(int i=0;i<nkb;i++){
        asm volatile("cp.async.wait_group 2;");
        __syncthreads();
        const float* Ast=As+(i&3)*2304;
        const float* Bst=Bs+(i&3)*1280;
#pragma unroll
        for(int kc=0;kc<32;kc+=8){
            uint32_t ah[4], al[4];
            float v0=Ast[(16*mt+g)*36+kc+cl];
            float v1=Ast[(16*mt+8+g)*36+kc+cl];
            float v2=Ast[(16*mt+g)*36+kc+cl+4];
            float v3=Ast[(16*mt+8+g)*36+kc+cl+4];
            ah[0]=f2tf(v0); al[0]=f2tf(v0-__uint_as_float(ah[0]));
            ah[1]=f2tf(v1); al[1]=f2tf(v1-__uint_as_float(ah[1]));
            ah[2]=f2tf(v2); al[2]=f2tf(v2-__uint_as_float(ah[2]));
            ah[3]=f2tf(v3); al[3]=f2tf(v3-__uint_as_float(ah[3]));
#pragma unroll
            for(int nt=0;nt<2;nt++){
                int ncol=nh*16+nt*8+g;
                float b0=Bst[(kc+cl)*40+ncol], b1=Bst[(kc+cl+4)*40+ncol];
                uint32_t bh[2]={f2tf(b0), f2tf(b1)};
                uint32_t bl[2]={f2tf(b0-__uint_as_float(bh[0])),
                                f2tf(b1-__uint_as_float(bh[1]))};
                mma8(d[nt],ah,bh);
                mma8(d[nt],ah,bl);
                mma8(d[nt],al,bh);
            }
        }
        int nx=i+3;
        if(nx<nkb) LD(nx&3,nx*32);
        asm volatile("cp.async.commit_group;");
    }
#pragma unroll
    for(int nt=0;nt<2;nt++){
        int n0=nh*16+nt*8;
        Cs[(16*mt+g)*36+n0+2*cl]     = d[nt][0];
        Cs[(16*mt+g)*36+n0+2*cl+1]   = d[nt][1];
        Cs[(16*mt+8+g)*36+n0+2*cl]   = d[nt][2];
        Cs[(16*mt+8+g)*36+n0+2*cl+1] = d[nt][3];
    }
    __syncthreads();
    if(epi==0){
#pragma unroll
        for(int i=0;i<8;i++){
            int e=i*256+tid, m=e>>5, gc=e&31;
            o1[(size_t)m*ldo1 + n*32+gc] = Cs[m*36+gc] + bias[n*32+gc];
        }
    } else {
#pragma unroll
        for(int i=0;i<2;i++){
            int e=i*256+tid, m=e>>3, c=e&7;
            float r_ = sigm(Cs[m*36+c]     + bias[n*32+c]);
            float z  = sigm(Cs[m*36+8+c]   + bias[n*32+8+c]);
            float nn = tanhf(Cs[m*36+16+c] + bias[n*32+16+c]
                             + r_*(Cs[m*36+24+c] + bias[n*32+24+c]));
            int j=n*8+c;
            float hv=(1.f-z)*nn + z*hold[(size_t)m*ldh+j];
            o1[(size_t)m*ldo1+j]=hv;
            o2[(size_t)m*ldo2+j]=rnd2?rnd(hv):hv;
        }
    }
    __syncthreads();
}

// ---------- persistent decode loop (256 thr; merged attention phase) ----------
__global__ __launch_bounds__(256) void k_loop(
    const float* __restrict__ abq, const float* __restrict__ av)
{
    extern __shared__ float sp[];
    float* As  = sp;               // 4*2304
    float* Bs  = As+4*2304;        // 4*1280
    float* Cs  = Bs+4*1280;        // 2304
    float* sred= Cs+2304;          // 256
    float* sw  = sred+256;         // 200
    float* se  = sw+200;           // 200
    const int bid=blockIdx.x, tid=threadIdx.x;
    const int w=tid>>5, lane=tid&31;

    for(int t=0;t<cTS;t++){
        const int p=t&1, pp=p^1;
        float* c0=g_cat0+p*64*3072;  float* d0=g_cat0+pp*64*3072;
        float* c1=g_cat1+p*64*2048;  float* d1=g_cat1+pp*64*2048;
        float* c2=g_cat2+p*64*2048;  float* d2=g_cat2+pp*64*2048;
        float* c3=g_cat3+p*64*2048;  float* d3=g_cat3+pp*64*2048;

        // A: q = h3 @ Wq + bq (32 strips)
        if(bid<32)
            strip_gemm(0,bid, c3+1024,2048,1024, g_Wqp,32,1024*32, abq,
                       0,0, g_q,1024, g_q,1024, 0, As,Bs,Cs);
        gbar();

        // B: merged attention — one batch per block (64 blocks)
        if(bid<64){
            const int b=bid;
            const float* qr=g_q+(size_t)b*1024;
            // scores -> se[196]
            for(int r=w; r<cS; r+=8){
                const float* kr=g_kf+((size_t)(b*cS+r))*2048;
                float acc=0.f;
#pragma unroll 4
                for(int h=lane;h<1024;h+=32) acc+=tanha(qr[h]+kr[h])*av[h];
#pragma unroll
                for(int o=16;o;o>>=1) acc+=__shfl_down_sync(0xffffffffu,acc,o);
                if(lane==0) se[r]=acc;
            }
            __syncthreads();
            // softmax (identical value order to R11)
            float v=(tid<cS)?se[tid]:-1e30f;
            sred[tid]=v; __syncthreads();
            for(int o=128;o;o>>=1){ if(tid<o) sred[tid]=fmaxf(sred[tid],sred[tid+o]); __syncthreads(); }
            float mx=sred[0]; __syncthreads();
            float ev=(tid<cS)?expf(v-mx):0.f;
            sred[tid]=ev; __syncthreads();
            for(int o=128;o;o>>=1){ if(tid<o) sred[tid]+=sred[tid+o]; __syncthreads(); }
            float inv=1.f/sred[0];
            if(tid<cS) sw[tid]=ev*inv;
            __syncthreads();
            // ctx + x copy: 4 cols per thread (same per-column order as R11)
#pragma unroll
            for(int i=0;i<4;i++){
                int h=i*256+tid;
                const float* f=g_kf+(size_t)b*cS*2048+1024+h;
                float a0=0.f,a1=0.f,a2=0.f,a3=0.f;
#pragma unroll 1
                for(int s=0;s<cS;s+=4){
                    a0+=sw[s+0]*f[(size_t)(s+0)*2048];
                    a1+=sw[s+1]*f[(size_t)(s+1)*2048];
                    a2+=sw[s+2]*f[(size_t)(s+2)*2048];
                    a3+=sw[s+3]*f[(size_t)(s+3)*2048];
                }
                c0[b*3072+1024+h]=(a0+a1)+(a2+a3);
                c0[b*3072+h]=g_xseq[(size_t)(t*64+b)*1024+h];
            }
            __syncthreads();
        }
        gbar();

        // D-G: GRU stack (128 strips each)
        if(bid<128)
            strip_gemm(1,bid, c0,3072,3072, g_Bp0,32,3072*32, g_biasp,
                       c0+2048,3072, d0+2048,3072, c1,2048, 0, As,Bs,Cs);
        gbar();
        if(bid<128)
            strip_gemm(1,bid, c1,2048,2048, g_Bp123,32,2048*32, g_biasp+4096,
                       c1+1024,2048, d1+1024,2048, c2,2048, 0, As,Bs,Cs);
        gbar();
        if(bid<128)
            strip_gemm(1,bid, c2,2048,2048, g_Bp123+LSZ,32,2048*32, g_biasp+8192,
                       c2+1024,2048, d2+1024,2048, c3,2048, 0, As,Bs,Cs);
        gbar();
        if(bid<128)
            strip_gemm(1,bid, c3,2048,2048, g_Bp123+2*LSZ,32,2048*32, g_biasp+12288,
                       c3+1024,2048, d3+1024,2048, g_hall+(size_t)t*64*1024,1024, 1, As,Bs,Cs);
        gbar();
    }
}

// ---------- ONE fused setup kernel (all packing/rounding/embed/zero) ----------
__global__ void k_setup(
    const float* __restrict__ features, const int* __restrict__ captions,
    const int* __restrict__ sos, const float* __restrict__ emb,
    const float* __restrict__ fc1W, const float* __restrict__ aWq,
    const float* __restrict__ aWk, const float* __restrict__ abk,
    const float* __restrict__ fc0W, const float* __restrict__ fc0b,
    const float* __restrict__ Wi0, const float* __restrict__ Wh0,
    const float* __restrict__ bi0, const float* __restrict__ bh0,
    const float* __restrict__ Wi, const float* __restrict__ Wh,
    const float* __restrict__ bi, const float* __restrict__ bh,
    const float* __restrict__ fc2W)
{
    const int gt=blockIdx.x*blockDim.x+threadIdx.x;
    const int gs=gridDim.x*blockDim.x;

    // packcat + bcat
    for(int idx=gt; idx<2048*2048; idx+=gs){
        int k=idx>>11, c=idx&2047;
        g_Bcat[idx]=rnd((c<1024)?aWk[k*1024+c]:fc0W[k*1024+c-1024]);
        if(idx<2048) g_bcat[idx]=(idx<1024)?abk[idx]:fc0b[idx-1024];
    }
    // featR
    for(int idx=gt; idx<BSR*2048; idx+=gs) g_featR[idx]=rnd(features[idx]);
    // fc1R
    for(int idx=gt; idx<512*1024; idx+=gs) g_fc1R[idx]=rnd(fc1W[idx]);
    // fc2R
    for(int idx=gt; idx<1024*10000; idx+=gs) g_fc2R[idx]=rnd(fc2W[idx]);
    // pack0
    for(int idx=gt; idx<L0SZ; idx+=gs){
        int n=idx/(3072*32), r=idx%(3072*32);
        int k=r>>5, gc=r&31, g=gc>>3, c=gc&7, j=n*8+c;
        float v=0.f;
        if(k<2048){ if(g<3) v=Wi0[(size_t)(g*1024+j)*2048+k]; }
        else { int kh=k-2048;
            if(g<2) v=Wh0[(size_t)(g*1024+j)*1024+kh];
            else if(g==3) v=Wh0[(size_t)(2048+j)*1024+kh]; }
        g_Bp0[idx]=v;
    }
    // pack123 (z folded in)
    for(int q=gt; q<3*LSZ; q+=gs){
        int z=q/LSZ, idx=q%LSZ;
        const float* wi=Wi+(size_t)z*3072*1024;
        const float* wh=Wh+(size_t)z*3072*1024;
        int n=idx/(2048*32), r=idx%(2048*32);
        int k=r>>5, gc=r&31, g=gc>>3, c=gc&7, j=n*8+c;
        float v=0.f;
        if(k<1024){ if(g<3) v=wi[(size_t)(g*1024+j)*1024+k]; }
        else { int kh=k-1024;
            if(g<2) v=wh[(size_t)(g*1024+j)*1024+kh];
            else if(g==3) v=wh[(size_t)(2048+j)*1024+kh]; }
        g_Bp123[q]=v;
    }
    // packq
    for(int idx=gt; idx<QSZ; idx+=gs){
        int n=idx/(1024*32), r=idx%(1024*32), k=r>>5, c=r&31;
        g_Wqp[idx]=aWq[(size_t)k*1024 + n*32+c];
    }
    // packbias
    for(int idx=gt; idx<4*4096; idx+=gs){
        int l=idx>>12, r=idx&4095;
        int n=r>>5, gc=r&31, g=gc>>3, c=gc&7, j=n*8+c;
        const float* bx =(l==0)?bi0:bi+(l-1)*3072;
        const float* bhx=(l==0)?bh0:bh+(l-1)*3072;
        float v;
        if(g==0)      v=bx[j]+bhx[j];
        else if(g==1) v=bx[1024+j]+bhx[1024+j];
        else if(g==2) v=bx[2048+j];
        else          v=bhx[2048+j];
        g_biasp[idx]=v;
    }
    // zero hidden slots
    for(int idx=gt; idx<4*64*1024; idx+=gs){
        int reg=idx>>16, q=idx&65535, m=q>>10, j=q&1023;
        if(reg==0)      g_cat0[m*3072+2048+j]=0.f;
        else if(reg==1) g_cat1[m*2048+1024+j]=0.f;
        else if(reg==2) g_cat2[m*2048+1024+j]=0.f;
        else            g_cat3[m*2048+1024+j]=0.f;
    }
    // embed (rounded)
    for(int idx=gt; idx<MT*cE; idx+=gs){
        int r=idx/cE, i=idx%cE;
        int tt=r>>6, b=r&63;
        int tok=(tt==0)?*sos:captions[b*cT+tt];
        g_xemb[idx]=rnd(emb[(size_t)tok*cE+i]);
    }
}

extern "C" void kernel_launch(void* const* d_in, const int* in_sizes, int n_in,
                              void* d_out, int out_size)
{
    const float* features=(const float*)d_in[0];
    const int*   captions=(const int*)d_in[1];
    const int*   sos     =(const int*)d_in[2];
    const float* emb     =(const float*)d_in[3];
    const float* fc1W=(const float*)d_in[4];  const float* fc1b=(const float*)d_in[5];
    const float* aWq =(const float*)d_in[6];  const float* abq =(const float*)d_in[7];
    const float* aWk =(const float*)d_in[8];  const float* abk =(const float*)d_in[9];
    const float* av  =(const float*)d_in[10];
    const float* fc0W=(const float*)d_in[12]; const float* fc0b=(const float*)d_in[13];
    const float* Wi0 =(const float*)d_in[14]; const float* Wh0 =(const float*)d_in[15];
    const float* bi0 =(const float*)d_in[16]; const float* bh0 =(const float*)d_in[17];
    const float* Wi  =(const float*)d_in[18]; const float* Wh  =(const float*)d_in[19];
    const float* bi  =(const float*)d_in[20]; const float* bh  =(const float*)d_in[21];
    const float* fc2W=(const float*)d_in[22]; const float* fc2b=(const float*)d_in[23];
    float* out=(float*)d_out;

    float *pBcat,*pbcat,*pfeatR,*pfc1R,*pfc2R,*pkf,*pxemb,*pxseq,*phall;
    cudaGetSymbolAddress((void**)&pBcat,  g_Bcat);
    cudaGetSymbolAddress((void**)&pbcat,  g_bcat);
    cudaGetSymbolAddress((void**)&pfeatR, g_featR);
    cudaGetSymbolAddress((void**)&pfc1R,  g_fc1R);
    cudaGetSymbolAddress((void**)&pfc2R,  g_fc2R);
    cudaGetSymbolAddress((void**)&pkf,    g_kf);
    cudaGetSymbolAddress((void**)&pxemb,  g_xemb);
    cudaGetSymbolAddress((void**)&pxseq,  g_xseq);
    cudaGetSymbolAddress((void**)&phall,  g_hall);

    static bool attr_set=false;
    if(!attr_set){
        cudaFuncSetAttribute(k_loop, cudaFuncAttributeMaxDynamicSharedMemorySize, 70656);
        attr_set=true;
    }

    // launch order: k_loop is launch #4 (ncu target)
    k_setup<<<1184,256>>>(features,captions,sos,emb,fc1W,aWq,aWk,abk,fc0W,fc0b,
                          Wi0,Wh0,bi0,bh0,Wi,Wh,bi,bh,fc2W);                 // 1
    k_mm<0><<<dim3(16,98),256>>>(pfeatR,pBcat,pkf,BSR,2048,2048,pbcat);      // 2
    k_mm<0><<<dim3(8,8),256>>>(pxemb,pfc1R,pxseq,MT,cH,cE,fc1b);             // 3
    k_loop<<<NB,256,69184>>>(abq,av);                                        // 4 <- profile
    k_mm<2><<<dim3(79,8),256>>>(phall,pfc2R,out,MT,cV,cH,fc2b);              // 5
}

// round 16
// speedup vs baseline: 1.2821x; 1.2821x over previous
#include <cuda_runtime.h>
#include <math.h>
#include <stdint.h>

constexpr int cB=64, cS=196, cH=1024, cK=2048, cV=10000, cE=512, cT=16, cTS=15;
constexpr int BSR = cB*cS;            // 12544
constexpr int MT  = cTS*cB;           // 960
constexpr int L0SZ = 128*3072*32;
constexpr int LSZ  = 128*2048*32;
constexpr int QSZ  = 32*1024*32;
constexpr int NB   = 148;

__device__ unsigned g_cnt, g_gen;

__device__ float g_Bp0[L0SZ];
__device__ float g_Bp123[3*LSZ];
__device__ float g_Wqp[QSZ];
__device__ float g_biasp[4*4096];
__device__ float g_Bcat[2048*2048];   // rounded
__device__ float g_bcat[2048];
__device__ float g_featR[BSR*2048];   // rounded features
__device__ float g_fc1R[512*1024];
__device__ float g_fc2R[1024*10000];
__device__ float g_kf[BSR*2048];      // [keys | feat0]
__device__ float g_xemb[MT*cE];       // rounded
__device__ float g_xseq[MT*cH];
__device__ float g_cat0[2*64*3072];
__device__ float g_cat1[2*64*2048];
__device__ float g_cat2[2*64*2048];
__device__ float g_cat3[2*64*2048];
__device__ float g_q[64*1024];
__device__ float g_e[64*cS];
__device__ float g_hall[MT*cH];       // rounded (epilogue)

__device__ __forceinline__ uint32_t f2tf(float f){
    uint32_t u; asm("cvt.rna.tf32.f32 %0,%1;":"=r"(u):"f"(f)); return u;
}
__device__ __forceinline__ float rnd(float f){ return __uint_as_float(f2tf(f)); }
__device__ __forceinline__ void mma8(float* d, const uint32_t* a, const uint32_t* b){
    asm volatile("mma.sync.aligned.m16n8k8.row.col.f32.tf32.tf32.f32 "
        "{%0,%1,%2,%3},{%4,%5,%6,%7},{%8,%9},{%0,%1,%2,%3};"
        : "+f"(d[0]),"+f"(d[1]),"+f"(d[2]),"+f"(d[3])
        : "r"(a[0]),"r"(a[1]),"r"(a[2]),"r"(a[3]),"r"(b[0]),"r"(b[1]));
}
__device__ __forceinline__ void cpa(void* s, const void* g){
    unsigned sa=(unsigned)__cvta_generic_to_shared(s);
    asm volatile("cp.async.ca.shared.global [%0],[%1],16;"::"r"(sa),"l"(g));
}
__device__ __forceinline__ void cpaz(void* s, const void* g, bool p){
    unsigned sa=(unsigned)__cvta_generic_to_shared(s);
    int sz=p?16:0;
    asm volatile("cp.async.ca.shared.global [%0],[%1],16,%2;"::"r"(sa),"l"(g),"r"(sz));
}
__device__ __forceinline__ float sigm(float x){ return 1.f/(1.f+expf(-x)); }
__device__ __forceinline__ float tanha(float x){
    float y; asm("tanh.approx.f32 %0,%1;":"=f"(y):"f"(x)); return y;
}

// ---------- replay-safe grid barrier ----------
__device__ __forceinline__ void gbar(){
    __syncthreads();
    if(threadIdx.x==0){
        __threadfence();
        unsigned g=*((volatile unsigned*)&g_gen);
        if(atomicAdd(&g_cnt,1)==gridDim.x-1){
            g_cnt=0;
            __threadfence();
            atomicAdd(&g_gen,1);
        } else {
            while(*((volatile unsigned*)&g_gen)==g){}
            __threadfence();
        }
    }
    __syncthreads();
}

// ---------- big tf32 GEMM (pre-rounded inputs; Bs padded conflict-free) ----------
template<int MODE>
__global__ __launch_bounds__(256) void k_mm(
    const float* __restrict__ A, const float* __restrict__ B,
    float* __restrict__ C, int M, int N, int K, const float* __restrict__ bias)
{
    __shared__ __align__(16) float As[4][128][20];
    __shared__ __align__(16) float Bs[4][16][136];
    const int tid=threadIdx.x, w=tid>>5, lane=tid&31, g=lane>>2, cl=lane&3;
    const int m0=blockIdx.y*128, n0=blockIdx.x*128;
    const int wm=(w>>2)*64, wn=(w&3)*32;
    float d[4][4][4];
#pragma unroll
    for(int mi=0;mi<4;mi++)
#pragma unroll
        for(int ni=0;ni<4;ni++)
#pragma unroll
            for(int k=0;k<4;k++) d[mi][ni][k]=0.f;

    const int nk=K>>4;
    auto LD=[&](int s,int kb){
#pragma unroll
        for(int i=0;i<2;i++){
            int r=i*64+(tid>>2), ch=(tid&3)*4;
            bool p=(m0+r)<M;
            int row=p?(m0+r):0;
            cpaz(&As[s][r][ch], A+(size_t)row*K+kb+ch, p);
        }
#pragma unroll
        for(int i=0;i<2;i++){
            int id=i*256+tid, r=id>>5, ch=(id&31)*4;
            bool p=(n0+ch)<N;
            int col=p?(n0+ch):0;
            cpaz(&Bs[s][r][ch], B+(size_t)(kb+r)*N+col, p);
        }
    };
#pragma unroll
    for(int s=0;s<3;s++){
        if(s<nk) LD(s,s*16);
        asm volatile("cp.async.commit_group;");
    }
    for(int i=0;i<nk;i++){
        asm volatile("cp.async.wait_group 2;");
        __syncthreads();
        const int st=i&3;
#pragma unroll
        for(int kc=0;kc<16;kc+=8){
            uint32_t a[4][4], b[4][2];
#pragma unroll
            for(int mi=0;mi<4;mi++){
                a[mi][0]=__float_as_uint(As[st][wm+16*mi+g][kc+cl]);
                a[mi][1]=__float_as_uint(As[st][wm+16*mi+8+g][kc+cl]);
                a[mi][2]=__float_as_uint(As[st][wm+16*mi+g][kc+cl+4]);
                a[mi][3]=__float_as_uint(As[st][wm+16*mi+8+g][kc+cl+4]);
            }
#pragma unroll
            for(int ni=0;ni<4;ni++){
                b[ni][0]=__float_as_uint(Bs[st][kc+cl][wn+8*ni+g]);
                b[ni][1]=__float_as_uint(Bs[st][kc+cl+4][wn+8*ni+g]);
            }
#pragma unroll
            for(int mi=0;mi<4;mi++)
#pragma unroll
                for(int ni=0;ni<4;ni++) mma8(d[mi][ni],a[mi],b[ni]);
        }
        int nx=i+3;
        if(nx<nk) LD(nx&3,nx*16);
        asm volatile("cp.async.commit_group;");
    }
#pragma unroll
    for(int mi=0;mi<4;mi++)
#pragma unroll
        for(int ni=0;ni<4;ni++)
#pragma unroll
            for(int k=0;k<4;k++){
                int row=m0+wm+16*mi+g+((k>=2)?8:0);
                int col=n0+wn+8*ni+2*cl+(k&1);
                if(row<M && col<N){
                    float v=d[mi][ni][k]+bias[col];
                    if(MODE==0) C[(size_t)row*N+col]=v;
                    else        C[(size_t)((row&63)*cTS+(row>>6))*N+col]=v;
                }
            }
}

// ---------- strip GEMM: BK=64, 2-stage double buffer (same k/FMA order) ----------
// epi 0: o1[m*ldo1 + n*32+gc] = C + bias.   epi 1: GRU update -> o1,o2 (cols n*8+c).
__device__ void strip_gemm(int epi, int n,
    const float* __restrict__ A, int lda, int KA,
    const float* __restrict__ Bg, int ldb, int boff,
    const float* __restrict__ bias,
    const float* __restrict__ hold, int ldh,
    float* __restrict__ o1, int ldo1,
    float* __restrict__ o2, int ldo2, int rnd2,
    float* As, float* Bs, float* Cs)
{
    const int tid=threadIdx.x;
    const float* Bblk=Bg+(size_t)n*boff;
    const int w=tid>>5, lane=tid&31, g=lane>>2, cl=lane&3;
    const int mt=w&3, nh=w>>2;
    float d[2][4]={{0.f,0.f,0.f,0.f},{0.f,0.f,0.f,0.f}};
    const int nkb=KA>>6;                 // BK=64
    // A stage: 64 x 68 floats (stride 68).  B stage: 64 x 40 floats.
    auto LD=[&](int s,int kb){
#pragma unroll
        for(int i=0;i<4;i++){
            int q=i*256+tid, r=q>>4, ch=(q&15)*4;
            cpa(As+s*4352+r*68+ch, A+(size_t)r*lda+kb+ch);
        }
#pragma unroll
        for(int i=0;i<2;i++){
            int q=i*256+tid, r=q>>3, ch=(q&7)*4;
            cpa(Bs+s*2560+r*40+ch, Bblk+(size_t)(kb+r)*ldb+ch);
        }
    };
    LD(0,0);
    asm volatile("cp.async.commit_group;");
    for(int i=0;i<nkb;i++){
        if(i+1<nkb){
            LD((i+1)&1,(i+1)*64);
            asm volatile("cp.async.commit_group;");
            asm volatile("cp.async.wait_group 1;");
        } else {
            asm volatile("cp.async.wait_group 0;");
        }
        __syncthreads();
        const float* Ast=As+(i&1)*4352;
        const float* Bst=Bs+(i&1)*2560;
#pragma unroll
        for(int kc=0;kc<64;kc+=8){
            uint32_t ah[4], al[4];
            float v0=Ast[(16*mt+g)*68+kc+cl];
            float v1=Ast[(16*mt+8+g)*68+kc+cl];
            float v2=Ast[(16*mt+g)*68+kc+cl+4];
            float v3=Ast[(16*mt+8+g)*68+kc+cl+4];
            ah[0]=f2tf(v0); al[0]=f2tf(v0-__uint_as_float(ah[0]));
            ah[1]=f2tf(v1); al[1]=f2tf(v1-__uint_as_float(ah[1]));
            ah[2]=f2tf(v2); al[2]=f2tf(v2-__uint_as_float(ah[2]));
            ah[3]=f2tf(v3); al[3]=f2tf(v3-__uint_as_float(ah[3]));
#pragma unroll
            for(int nt=0;nt<2;nt++){
                int ncol=nh*16+nt*8+g;
                float b0=Bst[(kc+cl)*40+ncol], b1=Bst[(kc+cl+4)*40+ncol];
                uint32_t bh[2]={f2tf(b0), f2tf(b1)};
                uint32_t bl[2]={f2tf(b0-__uint_as_float(bh[0])),
                                f2tf(b1-__uint_as_float(bh[1]))};
                mma8(d[nt],ah,bh);
                mma8(d[nt],ah,bl);
                mma8(d[nt],al,bh);
            }
        }
        __syncthreads();
    }
#pragma unroll
    for(int nt=0;nt<2;nt++){
        int n0=nh*16+nt*8;
        Cs[(16*mt+g)*36+n0+2*cl]     = d[nt][0];
        Cs[(16*mt+g)*36+n0+2*cl+1]   = d[nt][1];
        Cs[(16*mt+8+g)*36+n0+2*cl]   = d[nt][2];
        Cs[(16*mt+8+g)*36+n0+2*cl+1] = d[nt][3];
    }
    __syncthreads();
    if(epi==0){
#pragma unroll
        for(int i=0;i<8;i++){
            int e=i*256+tid, m=e>>5, gc=e&31;
            o1[(size_t)m*ldo1 + n*32+gc] = Cs[m*36+gc] + bias[n*32+gc];
        }
    } else {
#pragma unroll
        for(int i=0;i<2;i++){
            int e=i*256+tid, m=e>>3, c=e&7;
            float r_ = sigm(Cs[m*36+c]     + bias[n*32+c]);
            float z  = sigm(Cs[m*36+8+c]   + bias[n*32+8+c]);
            float nn = tanhf(Cs[m*36+16+c] + bias[n*32+16+c]
                             + r_*(Cs[m*36+24+c] + bias[n*32+24+c]));
            int j=n*8+c;
            float hv=(1.f-z)*nn + z*hold[(size_t)m*ldh+j];
            o1[(size_t)m*ldo1+j]=hv;
            o2[(size_t)m*ldo2+j]=rnd2?rnd(hv):hv;
        }
    }
    __syncthreads();
}

// ---------- persistent decode loop (R11 structure; 66.3 KB dyn smem) ----------
__global__ __launch_bounds__(256) void k_loop(
    const float* __restrict__ abq, const float* __restrict__ av)
{
    extern __shared__ float sp[];
    float* As  = sp;               // 2*4352
    float* Bs  = As+2*4352;        // 2*2560
    float* Cs  = Bs+2*2560;        // 2304
    float* sred= Cs+2304;          // 256
    float* sw  = sred+256;         // 200
    const int bid=blockIdx.x, tid=threadIdx.x;
    const int w=tid>>5, lane=tid&31;

    for(int t=0;t<cTS;t++){
        const int p=t&1, pp=p^1;
        float* c0=g_cat0+p*64*3072;  float* d0=g_cat0+pp*64*3072;
        float* c1=g_cat1+p*64*2048;  float* d1=g_cat1+pp*64*2048;
        float* c2=g_cat2+p*64*2048;  float* d2=g_cat2+pp*64*2048;
        float* c3=g_cat3+p*64*2048;  float* d3=g_cat3+pp*64*2048;

        // A: q = h3 @ Wq + bq (32 strips)
        if(bid<32)
            strip_gemm(0,bid, c3+1024,2048,1024, g_Wqp,32,1024*32, abq,
                       0,0, g_q,1024, g_q,1024, 0, As,Bs,Cs);
        gbar();

        // B: scores (warp per row, all 148 blocks)
        for(int r=bid*8+w; r<BSR; r+=NB*8){
            const float* qr=g_q+(size_t)(r/cS)*1024;
            const float* kr=g_kf+(size_t)r*2048;
            float acc=0.f;
#pragma unroll 4
            for(int h=lane;h<1024;h+=32) acc+=tanha(qr[h]+kr[h])*av[h];
#pragma unroll
            for(int o=16;o;o>>=1) acc+=__shfl_down_sync(0xffffffffu,acc,o);
            if(lane==0) g_e[r]=acc;
        }
        gbar();

        // C: softmax(recompute) + ctx + x copy (256 units)
        for(int u=bid;u<256;u+=NB){
            int b=u>>2, h=(u&3)*256+tid;
            float v=(tid<cS)?g_e[b*cS+tid]:-1e30f;
            sred[tid]=v; __syncthreads();
            for(int o=128;o;o>>=1){ if(tid<o) sred[tid]=fmaxf(sred[tid],sred[tid+o]); __syncthreads(); }
            float mx=sred[0]; __syncthreads();
            float ev=(tid<cS)?expf(v-mx):0.f;
            sred[tid]=ev; __syncthreads();
            for(int o=128;o;o>>=1){ if(tid<o) sred[tid]+=sred[tid+o]; __syncthreads(); }
            float inv=1.f/sred[0];
            if(tid<cS) sw[tid]=ev*inv;
            __syncthreads();
            const float* f=g_kf+(size_t)b*cS*2048+1024+h;
            float a0=0.f,a1=0.f,a2=0.f,a3=0.f;
#pragma unroll 1
            for(int s=0;s<cS;s+=4){
                a0+=sw[s+0]*f[(size_t)(s+0)*2048];
                a1+=sw[s+1]*f[(size_t)(s+1)*2048];
                a2+=sw[s+2]*f[(size_t)(s+2)*2048];
                a3+=sw[s+3]*f[(size_t)(s+3)*2048];
            }
            c0[b*3072+1024+h]=(a0+a1)+(a2+a3);
            c0[b*3072+h]=g_xseq[(size_t)(t*64+b)*1024+h];
            __syncthreads();
        }
        gbar();

        // D-G: GRU stack (128 strips each)
        if(bid<128)
            strip_gemm(1,bid, c0,3072,3072, g_Bp0,32,3072*32, g_biasp,
                       c0+2048,3072, d0+2048,3072, c1,2048, 0, As,Bs,Cs);
        gbar();
        if(bid<128)
            strip_gemm(1,bid, c1,2048,2048, g_Bp123,32,2048*32, g_biasp+4096,
                       c1+1024,2048, d1+1024,2048, c2,2048, 0, As,Bs,Cs);
        gbar();
        if(bid<128)
            strip_gemm(1,bid, c2,2048,2048, g_Bp123+LSZ,32,2048*32, g_biasp+8192,
                       c2+1024,2048, d2+1024,2048, c3,2048, 0, As,Bs,Cs);
        gbar();
        if(bid<128)
            strip_gemm(1,bid, c3,2048,2048, g_Bp123+2*LSZ,32,2048*32, g_biasp+12288,
                       c3+1024,2048, d3+1024,2048, g_hall+(size_t)t*64*1024,1024, 1, As,Bs,Cs);
        gbar();
    }
}

// ---------- setup ----------
__global__ void k_round(const float* __restrict__ src, float* __restrict__ dst, int n)
{
    for(int i=blockIdx.x*blockDim.x+threadIdx.x;i<n;i+=gridDim.x*blockDim.x)
        dst[i]=rnd(src[i]);
}

__global__ void k_embed(const int* __restrict__ captions, const int* __restrict__ sos,
                        const float* __restrict__ emb)
{
    int r=blockIdx.x, t=r>>6, b=r&63;
    int tok=(t==0)?*sos:captions[b*cT+t];
    const float* src=emb+(size_t)tok*cE;
    float* dst=g_xemb+(size_t)r*cE;
    for(int i=threadIdx.x;i<cE;i+=blockDim.x) dst[i]=rnd(src[i]);
}

__global__ void k_packcat(const float* __restrict__ aWk, const float* __restrict__ abk,
                          const float* __restrict__ fc0W, const float* __restrict__ fc0b)
{
    int idx=blockIdx.x*blockDim.x+threadIdx.x;
    if(idx>=2048*2048) return;
    int k=idx>>11, c=idx&2047;
    g_Bcat[idx]=rnd((c<1024)?aWk[k*1024+c]:fc0W[k*1024+c-1024]);
    if(idx<2048) g_bcat[idx]=(idx<1024)?abk[idx]:fc0b[idx-1024];
}

__global__ void k_pack0(const float* __restrict__ Wi0, const float* __restrict__ Wh0)
{
    int idx=blockIdx.x*blockDim.x+threadIdx.x;
    if(idx>=L0SZ) return;
    int n=idx/(3072*32), r=idx%(3072*32);
    int k=r>>5, gc=r&31, g=gc>>3, c=gc&7, j=n*8+c;
    float v=0.f;
    if(k<2048){ if(g<3) v=Wi0[(size_t)(g*1024+j)*2048+k]; }
    else { int kh=k-2048;
        if(g<2) v=Wh0[(size_t)(g*1024+j)*1024+kh];
        else if(g==3) v=Wh0[(size_t)(2048+j)*1024+kh]; }
    g_Bp0[idx]=v;
}

__global__ void k_pack123(const float* __restrict__ Wi, const float* __restrict__ Wh)
{
    int z=blockIdx.y;
    int idx=blockIdx.x*blockDim.x+threadIdx.x;
    if(idx>=LSZ) return;
    const float* wi=Wi+(size_t)z*3072*1024;
    const float* wh=Wh+(size_t)z*3072*1024;
    int n=idx/(2048*32), r=idx%(2048*32);
    int k=r>>5, gc=r&31, g=gc>>3, c=gc&7, j=n*8+c;
    float v=0.f;
    if(k<1024){ if(g<3) v=wi[(size_t)(g*1024+j)*1024+k]; }
    else { int kh=k-1024;
        if(g<2) v=wh[(size_t)(g*1024+j)*1024+kh];
        else if(g==3) v=wh[(size_t)(2048+j)*1024+kh]; }
    g_Bp123[(size_t)z*LSZ+idx]=v;
}

__global__ void k_packq(const float* __restrict__ Wq)
{
    int idx=blockIdx.x*blockDim.x+threadIdx.x;
    if(idx>=QSZ) return;
    int n=idx/(1024*32), r=idx%(1024*32), k=r>>5, c=r&31;
    g_Wqp[idx]=Wq[(size_t)k*1024 + n*32+c];
}

__global__ void k_packbias(const float* __restrict__ bi0, const float* __restrict__ bh0,
                           const float* __restrict__ bi, const float* __restrict__ bh)
{
    int idx=blockIdx.x*blockDim.x+threadIdx.x;
    if(idx>=4*4096) return;
    int l=idx>>12, r=idx&4095;
    int n=r>>5, gc=r&31, g=gc>>3, c=gc&7, j=n*8+c;
    const float* bx =(l==0)?bi0:bi+(l-1)*3072;
    const float* bhx=(l==0)?bh0:bh+(l-1)*3072;
    float v;
    if(g==0)      v=bx[j]+bhx[j];
    else if(g==1) v=bx[1024+j]+bhx[1024+j];
    else if(g==2) v=bx[2048+j];
    else          v=bhx[2048+j];
    g_biasp[idx]=v;
}

__global__ void k_zeroh()
{
    int idx=blockIdx.x*blockDim.x+threadIdx.x;
    if(idx>=4*64*1024) return;
    int reg=idx>>16, q=idx&65535, m=q>>10, j=q&1023;
    if(reg==0)      g_cat0[m*3072+2048+j]=0.f;
    else if(reg==1) g_cat1[m*2048+1024+j]=0.f;
    else if(reg==2) g_cat2[m*2048+1024+j]=0.f;
    else            g_cat3[m*2048+1024+j]=0.f;
}

extern "C" void kernel_launch(void* const* d_in, const int* in_sizes, int n_in,
                              void* d_out, int out_size)
{
    const float* features=(const float*)d_in[0];
    const int*   captions=(const int*)d_in[1];
    const int*   sos     =(const int*)d_in[2];
    const float* emb     =(const float*)d_in[3];
    const float* fc1W=(const float*)d_in[4];  const float* fc1b=(const float*)d_in[5];
    const float* aWq =(const float*)d_in[6];  const float* abq =(const float*)d_in[7];
    const float* aWk =(const float*)d_in[8];  const float* abk =(const float*)d_in[9];
    const float* av  =(const float*)d_in[10];
    const float* fc0W=(const float*)d_in[12]; const float* fc0b=(const float*)d_in[13];
    const float* Wi0 =(const float*)d_in[14]; const float* Wh0 =(const float*)d_in[15];
    const float* bi0 =(const float*)d_in[16]; const float* bh0 =(const float*)d_in[17];
    const float* Wi  =(const float*)d_in[18]; const float* Wh  =(const float*)d_in[19];
    const float* bi  =(const float*)d_in[20]; const float* bh  =(const float*)d_in[21];
    const float* fc2W=(const float*)d_in[22]; const float* fc2b=(const float*)d_in[23];
    float* out=(float*)d_out;

    float *pBcat,*pbcat,*pfeatR,*pfc1R,*pfc2R,*pkf,*pxemb,*pxseq,*phall;
    cudaGetSymbolAddress((void**)&pBcat,  g_Bcat);
    cudaGetSymbolAddress((void**)&pbcat,  g_bcat);
    cudaGetSymbolAddress((void**)&pfeatR, g_featR);
    cudaGetSymbolAddress((void**)&pfc1R,  g_fc1R);
    cudaGetSymbolAddress((void**)&pfc2R,  g_fc2R);
    cudaGetSymbolAddress((void**)&pkf,    g_kf);
    cudaGetSymbolAddress((void**)&pxemb,  g_xemb);
    cudaGetSymbolAddress((void**)&pxseq,  g_xseq);
    cudaGetSymbolAddress((void**)&phall,  g_hall);

    static bool attr_set=false;
    if(!attr_set){
        cudaFuncSetAttribute(k_loop, cudaFuncAttributeMaxDynamicSharedMemorySize, 69632);
        attr_set=true;
    }

    // launch order keeps the big kf GEMM at #4 for ncu
    k_packcat<<<16384,256>>>(aWk,abk,fc0W,fc0b);                            // 1
    k_round<<<2048,256>>>(features,pfeatR,BSR*2048);                        // 2
    k_round<<<512,256>>>(fc1W,pfc1R,512*1024);                              // 3
    k_mm<0><<<dim3(16,98),256>>>(pfeatR,pBcat,pkf,BSR,2048,2048,pbcat);     // 4 <- profile
    k_embed<<<MT,128>>>(captions,sos,emb);                                  // 5
    k_mm<0><<<dim3(8,8),256>>>(pxemb,pfc1R,pxseq,MT,cH,cE,fc1b);            // 6
    k_pack0<<<L0SZ/256,256>>>(Wi0,Wh0);                                     // 7
    k_pack123<<<dim3(LSZ/256,3),256>>>(Wi,Wh);                              // 8
    k_packbias<<<64,256>>>(bi0,bh0,bi,bh);                                  // 9
    k_packq<<<QSZ/256,256>>>(aWq);                                          // 10
    k_round<<<2048,256>>>(fc2W,pfc2R,1024*10000);                           // 11
    k_zeroh<<<1024,256>>>();                                                // 12

    k_loop<<<NB,256,66336>>>(abq,av);                                       // 13

    k_mm<2><<<dim3(79,8),256>>>(phall,pfc2R,out,MT,cV,cH,fc2b);             // 14
}